// round 2
// baseline (speedup 1.0000x reference)
#include <cuda_runtime.h>
#include <cuda_bf16.h>
#include <cstdint>

#define F_DIM 128
#define MAX_NODES 100000

// Scratch for y = x @ W^T  (51.2 MB). __device__ global per harness rules.
__device__ float g_y[(size_t)MAX_NODES * F_DIM];

// ---------------------------------------------------------------------------
// Kernel 1: y[n][o] = sum_k x[n][k] * W[o][k]
// Tile: M=64 nodes, N=128 outputs (full), K=16. 256 threads, 4x8 micro-tile.
// ---------------------------------------------------------------------------
__global__ __launch_bounds__(256, 4)
void gemm_xwt_kernel(const float* __restrict__ x, const float* __restrict__ W,
                     int n_nodes) {
    __shared__ float As[16][64];    // [k][m]
    __shared__ float Bs[16][128];   // [k][o]

    const int tid = threadIdx.x;
    const int m0  = blockIdx.x * 64;
    const int tx  = tid & 15;   // output-col group (8 cols each)
    const int ty  = tid >> 4;   // output-row group (4 rows each)

    float acc[4][8];
#pragma unroll
    for (int r = 0; r < 4; r++)
#pragma unroll
        for (int c = 0; c < 8; c++) acc[r][c] = 0.0f;

    const int am  = tid >> 2;        // 0..63  (node within tile)
    const int akq = (tid & 3) * 4;   // 0,4,8,12 (k quad)

    for (int k0 = 0; k0 < F_DIM; k0 += 16) {
        // Load A tile (x), transposed into [k][m]
        float4 av = make_float4(0.f, 0.f, 0.f, 0.f);
        const int gm = m0 + am;
        if (gm < n_nodes)
            av = *(const float4*)(x + (size_t)gm * F_DIM + k0 + akq);
        As[akq + 0][am] = av.x;
        As[akq + 1][am] = av.y;
        As[akq + 2][am] = av.z;
        As[akq + 3][am] = av.w;

        // Load B tile (W), transposed into [k][o]: 512 float4 total, 2/thread
#pragma unroll
        for (int i = 0; i < 2; i++) {
            const int idx = tid * 2 + i;       // 0..511
            const int bo  = idx >> 2;          // 0..127
            const int bkq = (idx & 3) * 4;     // 0,4,8,12
            float4 bv = *(const float4*)(W + (size_t)bo * F_DIM + k0 + bkq);
            Bs[bkq + 0][bo] = bv.x;
            Bs[bkq + 1][bo] = bv.y;
            Bs[bkq + 2][bo] = bv.z;
            Bs[bkq + 3][bo] = bv.w;
        }
        __syncthreads();

#pragma unroll
        for (int k = 0; k < 16; k++) {
            const float4 a  = *(const float4*)&As[k][ty * 4];
            const float4 b0 = *(const float4*)&Bs[k][tx * 8];
            const float4 b1 = *(const float4*)&Bs[k][tx * 8 + 4];
            const float avv[4] = {a.x, a.y, a.z, a.w};
            const float bvv[8] = {b0.x, b0.y, b0.z, b0.w,
                                  b1.x, b1.y, b1.z, b1.w};
#pragma unroll
            for (int r = 0; r < 4; r++)
#pragma unroll
                for (int c = 0; c < 8; c++)
                    acc[r][c] = fmaf(avv[r], bvv[c], acc[r][c]);
        }
        __syncthreads();
    }

#pragma unroll
    for (int r = 0; r < 4; r++) {
        const int gm = m0 + ty * 4 + r;
        if (gm < n_nodes) {
            float* dst = g_y + (size_t)gm * F_DIM + tx * 8;
            *(float4*)(dst)     = make_float4(acc[r][0], acc[r][1], acc[r][2], acc[r][3]);
            *(float4*)(dst + 4) = make_float4(acc[r][4], acc[r][5], acc[r][6], acc[r][7]);
        }
    }
}

// ---------------------------------------------------------------------------
// Kernel 2: out[n][f] = b[f]   (vectorized float4)
// ---------------------------------------------------------------------------
__global__ __launch_bounds__(256)
void init_bias_kernel(float4* __restrict__ out4, const float4* __restrict__ b4,
                      int total4) {
    const int i = blockIdx.x * blockDim.x + threadIdx.x;
    if (i < total4) out4[i] = b4[i & 31];   // 128 floats = 32 float4 per row
}

// ---------------------------------------------------------------------------
// Kernel 3: per edge e (one warp): out[rows[e]] += vals[e] * y[cols[e]]
// Each lane handles one float4 (4 floats) -> red.global.add.v4.f32
// ---------------------------------------------------------------------------
__global__ __launch_bounds__(256)
void scatter_kernel(const int* __restrict__ rows, const int* __restrict__ cols,
                    const float* __restrict__ vals, float* __restrict__ out,
                    int n_edges) {
    const int warp = (blockIdx.x * blockDim.x + threadIdx.x) >> 5;
    if (warp >= n_edges) return;
    const int lane = threadIdx.x & 31;

    int row = 0, col = 0;
    float val = 0.0f;
    if (lane == 0) {
        row = __ldg(rows + warp);
        col = __ldg(cols + warp);
        val = __ldg(vals + warp);
    }
    row = __shfl_sync(0xffffffffu, row, 0);
    col = __shfl_sync(0xffffffffu, col, 0);
    val = __shfl_sync(0xffffffffu, val, 0);

    const float4 v = *(const float4*)(g_y + (size_t)col * F_DIM + lane * 4);
    const float4 m = make_float4(v.x * val, v.y * val, v.z * val, v.w * val);

    float* dst = out + (size_t)row * F_DIM + lane * 4;
    asm volatile("red.global.add.v4.f32 [%0], {%1, %2, %3, %4};"
                 :: "l"(dst), "f"(m.x), "f"(m.y), "f"(m.z), "f"(m.w)
                 : "memory");
}

// ---------------------------------------------------------------------------
extern "C" void kernel_launch(void* const* d_in, const int* in_sizes, int n_in,
                              void* d_out, int out_size) {
    const int*   rows = (const int*)d_in[0];
    const int*   cols = (const int*)d_in[1];
    const float* vals = (const float*)d_in[2];
    const float* x    = (const float*)d_in[3];
    const float* W    = (const float*)d_in[4];
    const float* b    = (const float*)d_in[5];
    float*       out  = (float*)d_out;

    const int n_edges = in_sizes[0];
    const int n_nodes = in_sizes[3] / F_DIM;

    // 1) y = x @ W^T (independent of init; both precede scatter in stream order)
    {
        const int grid = (n_nodes + 63) / 64;
        gemm_xwt_kernel<<<grid, 256>>>(x, W, n_nodes);
    }
    // 2) out = broadcast(b)
    {
        const int total4 = n_nodes * (F_DIM / 4);
        const int grid = (total4 + 255) / 256;
        init_bias_kernel<<<grid, 256>>>((float4*)out, (const float4*)b, total4);
    }
    // 3) out[row] += val * y[col]  (one warp per edge)
    {
        const int warps_per_block = 256 / 32;
        const int grid = (n_edges + warps_per_block - 1) / warps_per_block;
        scatter_kernel<<<grid, 256>>>(rows, cols, vals, out, n_edges);
    }
}

// round 3
// speedup vs baseline: 1.1985x; 1.1985x over previous
#include <cuda_runtime.h>
#include <cuda_fp16.h>
#include <cstdint>

#define F_DIM 128
#define MAX_NODES 100000

// y = x @ W^T stored in fp16 (25.6 MB) — halves gather traffic, fits L2 with out.
__device__ __half g_yh[(size_t)MAX_NODES * F_DIM];

struct alignas(8) half4 { __half a, b, c, d; };

// ---------------------------------------------------------------------------
// Kernel 1: y[n][o] = sum_k x[n][k] * W[o][k], output fp16.
// 128x128 tile, K-tile 8, 256 threads, 8x8 micro-tile (2x2 of float4).
// ---------------------------------------------------------------------------
__global__ __launch_bounds__(256, 2)
void gemm_xwt_kernel(const float* __restrict__ x, const float* __restrict__ W,
                     int n_nodes) {
    __shared__ float As[8][128];   // [k][m]
    __shared__ float Bs[8][128];   // [k][o]

    const int tid = threadIdx.x;
    const int m0  = blockIdx.x * 128;
    const int tx  = tid & 15;      // 0..15 -> cols tx*4, tx*4+64
    const int ty  = tid >> 4;      // 0..15 -> rows ty*4, ty*4+64

    float acc[8][8];
#pragma unroll
    for (int r = 0; r < 8; r++)
#pragma unroll
        for (int c = 0; c < 8; c++) acc[r][c] = 0.0f;

    const int lr = tid >> 1;         // 0..127 (row within tile)
    const int lk = (tid & 1) * 4;    // 0 or 4 (k quad)

    for (int k0 = 0; k0 < F_DIM; k0 += 8) {
        // A tile: x[m0+lr][k0+lk .. +4) -> As[k][m]
        float4 av = make_float4(0.f, 0.f, 0.f, 0.f);
        const int gm = m0 + lr;
        if (gm < n_nodes)
            av = *(const float4*)(x + (size_t)gm * F_DIM + k0 + lk);
        As[lk + 0][lr] = av.x;
        As[lk + 1][lr] = av.y;
        As[lk + 2][lr] = av.z;
        As[lk + 3][lr] = av.w;

        // B tile: W[lr][k0+lk .. +4) -> Bs[k][o]  (F_OUT==128 always full)
        float4 bv = *(const float4*)(W + (size_t)lr * F_DIM + k0 + lk);
        Bs[lk + 0][lr] = bv.x;
        Bs[lk + 1][lr] = bv.y;
        Bs[lk + 2][lr] = bv.z;
        Bs[lk + 3][lr] = bv.w;

        __syncthreads();

#pragma unroll
        for (int k = 0; k < 8; k++) {
            const float4 a0 = *(const float4*)&As[k][ty * 4];
            const float4 a1 = *(const float4*)&As[k][ty * 4 + 64];
            const float4 b0 = *(const float4*)&Bs[k][tx * 4];
            const float4 b1 = *(const float4*)&Bs[k][tx * 4 + 64];
            const float ar[8] = {a0.x, a0.y, a0.z, a0.w, a1.x, a1.y, a1.z, a1.w};
            const float bc[8] = {b0.x, b0.y, b0.z, b0.w, b1.x, b1.y, b1.z, b1.w};
#pragma unroll
            for (int r = 0; r < 8; r++)
#pragma unroll
                for (int c = 0; c < 8; c++)
                    acc[r][c] = fmaf(ar[r], bc[c], acc[r][c]);
        }
        __syncthreads();
    }

    // Store as fp16: rows ty*4+{0..3} and +64; cols tx*4 and tx*4+64.
#pragma unroll
    for (int half_r = 0; half_r < 2; half_r++) {
#pragma unroll
        for (int r = 0; r < 4; r++) {
            const int gm = m0 + ty * 4 + half_r * 64 + r;
            if (gm >= n_nodes) continue;
            const int rr = half_r * 4 + r;
            __half* dst = g_yh + (size_t)gm * F_DIM;
            half4 h0 = { __float2half_rn(acc[rr][0]), __float2half_rn(acc[rr][1]),
                         __float2half_rn(acc[rr][2]), __float2half_rn(acc[rr][3]) };
            half4 h1 = { __float2half_rn(acc[rr][4]), __float2half_rn(acc[rr][5]),
                         __float2half_rn(acc[rr][6]), __float2half_rn(acc[rr][7]) };
            *(half4*)(dst + tx * 4)      = h0;
            *(half4*)(dst + tx * 4 + 64) = h1;
        }
    }
}

// ---------------------------------------------------------------------------
// Kernel 2: out[n][f] = b[f]
// ---------------------------------------------------------------------------
__global__ __launch_bounds__(256)
void init_bias_kernel(float4* __restrict__ out4, const float4* __restrict__ b4,
                      int total4) {
    const int i = blockIdx.x * blockDim.x + threadIdx.x;
    if (i < total4) out4[i] = b4[i & 31];
}

// ---------------------------------------------------------------------------
// Kernel 3: per edge (one warp): out[rows[e]] += vals[e] * y_fp16[cols[e]]
// Lane l: 4 features [l*4, l*4+4). Gather 8B fp16, red.global.add.v4.f32.
// ---------------------------------------------------------------------------
__global__ __launch_bounds__(256)
void scatter_kernel(const int* __restrict__ rows, const int* __restrict__ cols,
                    const float* __restrict__ vals, float* __restrict__ out,
                    int n_edges) {
    const int warp = (blockIdx.x * blockDim.x + threadIdx.x) >> 5;
    if (warp >= n_edges) return;
    const int lane = threadIdx.x & 31;

    int row = 0, col = 0;
    float val = 0.0f;
    if (lane == 0) {
        row = __ldg(rows + warp);
        col = __ldg(cols + warp);
        val = __ldg(vals + warp);
    }
    row = __shfl_sync(0xffffffffu, row, 0);
    col = __shfl_sync(0xffffffffu, col, 0);
    val = __shfl_sync(0xffffffffu, val, 0);

    const __half2* src = (const __half2*)(g_yh + (size_t)col * F_DIM) + lane * 2;
    const float2 f0 = __half22float2(src[0]);
    const float2 f1 = __half22float2(src[1]);

    float* dst = out + (size_t)row * F_DIM + lane * 4;
    asm volatile("red.global.add.v4.f32 [%0], {%1, %2, %3, %4};"
                 :: "l"(dst), "f"(f0.x * val), "f"(f0.y * val),
                    "f"(f1.x * val), "f"(f1.y * val)
                 : "memory");
}

// ---------------------------------------------------------------------------
extern "C" void kernel_launch(void* const* d_in, const int* in_sizes, int n_in,
                              void* d_out, int out_size) {
    const int*   rows = (const int*)d_in[0];
    const int*   cols = (const int*)d_in[1];
    const float* vals = (const float*)d_in[2];
    const float* x    = (const float*)d_in[3];
    const float* W    = (const float*)d_in[4];
    const float* b    = (const float*)d_in[5];
    float*       out  = (float*)d_out;

    const int n_edges = in_sizes[0];
    const int n_nodes = in_sizes[3] / F_DIM;

    // 1) y = x @ W^T -> fp16
    {
        const int grid = (n_nodes + 127) / 128;
        gemm_xwt_kernel<<<grid, 256>>>(x, W, n_nodes);
    }
    // 2) out = broadcast(b)
    {
        const int total4 = n_nodes * (F_DIM / 4);
        const int grid = (total4 + 255) / 256;
        init_bias_kernel<<<grid, 256>>>((float4*)out, (const float4*)b, total4);
    }
    // 3) scatter-accumulate
    {
        const int warps_per_block = 256 / 32;
        const int grid = (n_edges + warps_per_block - 1) / warps_per_block;
        scatter_kernel<<<grid, 256>>>(rows, cols, vals, out, n_edges);
    }
}

// round 4
// speedup vs baseline: 2.2187x; 1.8511x over previous
#include <cuda_runtime.h>
#include <cuda_fp16.h>
#include <cstdint>

#define F_DIM 128
#define MAX_NODES 100000
#define MAX_EDGES 3200000
#define SCAN_BLK 1024
#define MAX_SCAN_BLOCKS ((MAX_NODES + SCAN_BLK - 1) / SCAN_BLK + 2)

// Scratch (__device__ globals per harness rules)
__device__ float2 g_yh2[(size_t)MAX_NODES * (F_DIM / 4)]; // fp16 y, viewed as half2-pairs
__device__ int    g_count[MAX_NODES + 1];
__device__ int    g_start[MAX_NODES + 1];
__device__ int    g_cursor[MAX_NODES];
__device__ int    g_blocksums[MAX_SCAN_BLOCKS];
__device__ int2   g_edges[MAX_EDGES];          // packed (col, val-as-int)

struct alignas(8) half4 { __half a, b, c, d; };

// ---------------------------------------------------------------------------
// Kernel 1: y = x @ W^T -> fp16   (unchanged from R2: 85 us, proven)
// ---------------------------------------------------------------------------
__global__ __launch_bounds__(256, 2)
void gemm_xwt_kernel(const float* __restrict__ x, const float* __restrict__ W,
                     int n_nodes) {
    __shared__ float As[8][128];
    __shared__ float Bs[8][128];

    const int tid = threadIdx.x;
    const int m0  = blockIdx.x * 128;
    const int tx  = tid & 15;
    const int ty  = tid >> 4;

    float acc[8][8];
#pragma unroll
    for (int r = 0; r < 8; r++)
#pragma unroll
        for (int c = 0; c < 8; c++) acc[r][c] = 0.0f;

    const int lr = tid >> 1;
    const int lk = (tid & 1) * 4;

    for (int k0 = 0; k0 < F_DIM; k0 += 8) {
        float4 av = make_float4(0.f, 0.f, 0.f, 0.f);
        const int gm = m0 + lr;
        if (gm < n_nodes)
            av = *(const float4*)(x + (size_t)gm * F_DIM + k0 + lk);
        As[lk + 0][lr] = av.x;
        As[lk + 1][lr] = av.y;
        As[lk + 2][lr] = av.z;
        As[lk + 3][lr] = av.w;

        float4 bv = *(const float4*)(W + (size_t)lr * F_DIM + k0 + lk);
        Bs[lk + 0][lr] = bv.x;
        Bs[lk + 1][lr] = bv.y;
        Bs[lk + 2][lr] = bv.z;
        Bs[lk + 3][lr] = bv.w;

        __syncthreads();

#pragma unroll
        for (int k = 0; k < 8; k++) {
            const float4 a0 = *(const float4*)&As[k][ty * 4];
            const float4 a1 = *(const float4*)&As[k][ty * 4 + 64];
            const float4 b0 = *(const float4*)&Bs[k][tx * 4];
            const float4 b1 = *(const float4*)&Bs[k][tx * 4 + 64];
            const float ar[8] = {a0.x, a0.y, a0.z, a0.w, a1.x, a1.y, a1.z, a1.w};
            const float bc[8] = {b0.x, b0.y, b0.z, b0.w, b1.x, b1.y, b1.z, b1.w};
#pragma unroll
            for (int r = 0; r < 8; r++)
#pragma unroll
                for (int c = 0; c < 8; c++)
                    acc[r][c] = fmaf(ar[r], bc[c], acc[r][c]);
        }
        __syncthreads();
    }

    __half* yh = (__half*)g_yh2;
#pragma unroll
    for (int half_r = 0; half_r < 2; half_r++) {
#pragma unroll
        for (int r = 0; r < 4; r++) {
            const int gm = m0 + ty * 4 + half_r * 64 + r;
            if (gm >= n_nodes) continue;
            const int rr = half_r * 4 + r;
            __half* dst = yh + (size_t)gm * F_DIM;
            half4 h0 = { __float2half_rn(acc[rr][0]), __float2half_rn(acc[rr][1]),
                         __float2half_rn(acc[rr][2]), __float2half_rn(acc[rr][3]) };
            half4 h1 = { __float2half_rn(acc[rr][4]), __float2half_rn(acc[rr][5]),
                         __float2half_rn(acc[rr][6]), __float2half_rn(acc[rr][7]) };
            *(half4*)(dst + tx * 4)      = h0;
            *(half4*)(dst + tx * 4 + 64) = h1;
        }
    }
}

// ---------------------------------------------------------------------------
// Kernel 2: zero counters
// ---------------------------------------------------------------------------
__global__ void zero_count_kernel(int n_nodes) {
    const int i = blockIdx.x * blockDim.x + threadIdx.x;
    if (i <= n_nodes) g_count[i] = 0;
}

// ---------------------------------------------------------------------------
// Kernel 3: histogram of rows
// ---------------------------------------------------------------------------
__global__ __launch_bounds__(256)
void hist_kernel(const int* __restrict__ rows, int n_edges) {
    const int e = blockIdx.x * blockDim.x + threadIdx.x;
    if (e < n_edges) atomicAdd(&g_count[rows[e]], 1);
}

// ---------------------------------------------------------------------------
// Kernels 4-6: exclusive scan of g_count -> g_start (+ g_cursor copy)
// ---------------------------------------------------------------------------
__global__ __launch_bounds__(SCAN_BLK)
void scan1_kernel(int n) {
    __shared__ int s[SCAN_BLK];
    const int i = blockIdx.x * SCAN_BLK + threadIdx.x;
    const int v = (i < n) ? g_count[i] : 0;
    s[threadIdx.x] = v;
    __syncthreads();
#pragma unroll
    for (int d = 1; d < SCAN_BLK; d <<= 1) {
        int t = (threadIdx.x >= d) ? s[threadIdx.x - d] : 0;
        __syncthreads();
        s[threadIdx.x] += t;
        __syncthreads();
    }
    if (i < n) g_start[i] = s[threadIdx.x] - v;   // exclusive
    if (threadIdx.x == SCAN_BLK - 1) g_blocksums[blockIdx.x] = s[SCAN_BLK - 1];
}

__global__ void scan2_kernel(int nblocks, int n) {
    if (threadIdx.x == 0 && blockIdx.x == 0) {
        int acc = 0;
        for (int i = 0; i < nblocks; i++) {
            int t = g_blocksums[i];
            g_blocksums[i] = acc;
            acc += t;
        }
        g_start[n] = acc;  // total = n_edges
    }
}

__global__ __launch_bounds__(256)
void scan3_kernel(int n) {
    const int i = blockIdx.x * blockDim.x + threadIdx.x;
    if (i < n) {
        const int v = g_start[i] + g_blocksums[i >> 10];
        g_start[i]  = v;
        g_cursor[i] = v;
    }
}

// ---------------------------------------------------------------------------
// Kernel 7: reorder edges into row-buckets as (col, val)
// ---------------------------------------------------------------------------
__global__ __launch_bounds__(256)
void reorder_kernel(const int* __restrict__ rows, const int* __restrict__ cols,
                    const float* __restrict__ vals, int n_edges) {
    const int e = blockIdx.x * blockDim.x + threadIdx.x;
    if (e < n_edges) {
        const int r = rows[e];
        const int pos = atomicAdd(&g_cursor[r], 1);
        g_edges[pos] = make_int2(cols[e], __float_as_int(vals[e]));
    }
}

// ---------------------------------------------------------------------------
// Kernel 8: one warp per node: out[n] = b + sum_e val_e * y[col_e]
// Coalesced 32-edge batches; lane l owns features [4l, 4l+4).
// ---------------------------------------------------------------------------
__global__ __launch_bounds__(256)
void accum_kernel(const float* __restrict__ b, float* __restrict__ out,
                  int n_nodes) {
    const int node = (blockIdx.x * blockDim.x + threadIdx.x) >> 5;
    if (node >= n_nodes) return;
    const int lane = threadIdx.x & 31;

    const int s = g_start[node];
    const int e = g_start[node + 1];

    float a0 = 0.f, a1 = 0.f, a2 = 0.f, a3 = 0.f;

    for (int base = s; base < e; base += 32) {
        const int idx = base + lane;
        int2 ed = make_int2(0, 0);
        if (idx < e) ed = __ldg(&g_edges[idx]);
        const int cnt = min(32, e - base);

        if (cnt == 32) {
#pragma unroll 4
            for (int j = 0; j < 32; j++) {
                const int   col = __shfl_sync(0xffffffffu, ed.x, j);
                const float val = __int_as_float(__shfl_sync(0xffffffffu, ed.y, j));
                const float2 yv0 = __half22float2(((const __half2*)&g_yh2[(size_t)col * 32 + lane])[0]);
                const float2 yv1 = __half22float2(((const __half2*)&g_yh2[(size_t)col * 32 + lane])[1]);
                a0 = fmaf(yv0.x, val, a0);
                a1 = fmaf(yv0.y, val, a1);
                a2 = fmaf(yv1.x, val, a2);
                a3 = fmaf(yv1.y, val, a3);
            }
        } else {
            for (int j = 0; j < cnt; j++) {
                const int   col = __shfl_sync(0xffffffffu, ed.x, j);
                const float val = __int_as_float(__shfl_sync(0xffffffffu, ed.y, j));
                const float2 yv0 = __half22float2(((const __half2*)&g_yh2[(size_t)col * 32 + lane])[0]);
                const float2 yv1 = __half22float2(((const __half2*)&g_yh2[(size_t)col * 32 + lane])[1]);
                a0 = fmaf(yv0.x, val, a0);
                a1 = fmaf(yv0.y, val, a1);
                a2 = fmaf(yv1.x, val, a2);
                a3 = fmaf(yv1.y, val, a3);
            }
        }
    }

    const float4 bb = *(const float4*)(b + lane * 4);
    *(float4*)(out + (size_t)node * F_DIM + lane * 4) =
        make_float4(a0 + bb.x, a1 + bb.y, a2 + bb.z, a3 + bb.w);
}

// ---------------------------------------------------------------------------
extern "C" void kernel_launch(void* const* d_in, const int* in_sizes, int n_in,
                              void* d_out, int out_size) {
    const int*   rows = (const int*)d_in[0];
    const int*   cols = (const int*)d_in[1];
    const float* vals = (const float*)d_in[2];
    const float* x    = (const float*)d_in[3];
    const float* W    = (const float*)d_in[4];
    const float* b    = (const float*)d_in[5];
    float*       out  = (float*)d_out;

    const int n_edges = in_sizes[0];
    const int n_nodes = in_sizes[3] / F_DIM;
    const int nblocks_scan = (n_nodes + SCAN_BLK - 1) / SCAN_BLK;

    // 1) y = x @ W^T -> fp16
    gemm_xwt_kernel<<<(n_nodes + 127) / 128, 256>>>(x, W, n_nodes);

    // 2) zero counts
    zero_count_kernel<<<(n_nodes + 256) / 256, 256>>>(n_nodes);

    // 3) histogram
    hist_kernel<<<(n_edges + 255) / 256, 256>>>(rows, n_edges);

    // 4-6) exclusive scan -> g_start, g_cursor
    scan1_kernel<<<nblocks_scan, SCAN_BLK>>>(n_nodes);
    scan2_kernel<<<1, 32>>>(nblocks_scan, n_nodes);
    scan3_kernel<<<(n_nodes + 255) / 256, 256>>>(n_nodes);

    // 7) counting-sort edges into buckets
    reorder_kernel<<<(n_edges + 255) / 256, 256>>>(rows, cols, vals, n_edges);

    // 8) gather-accumulate (one warp per node), bias fused
    accum_kernel<<<(n_nodes * 32 + 255) / 256, 256>>>(b, out, n_nodes);
}

// round 5
// speedup vs baseline: 2.4369x; 1.0984x over previous
#include <cuda_runtime.h>
#include <cuda_fp16.h>
#include <cstdint>

#define F_DIM 128
#define MAX_NODES 100000
#define MAX_EDGES 3200000
#define SCAN_BLK 1024
#define MAX_SCAN_BLOCKS ((MAX_NODES + SCAN_BLK - 1) / SCAN_BLK + 2)

// Scratch (__device__ globals per harness rules)
__device__ float2 g_yh2[(size_t)MAX_NODES * (F_DIM / 4)]; // fp16 y (half2 pairs)
__device__ int    g_count[MAX_NODES + 1];
__device__ int    g_start[MAX_NODES + 1];
__device__ int    g_cursor[MAX_NODES];
__device__ int    g_blocksums[MAX_SCAN_BLOCKS];
__device__ int2   g_edges[MAX_EDGES];          // packed (col, val-as-int)

struct alignas(8) half4 { __half a, b, c, d; };

// ---------------------------------------------------------------------------
// Kernel 1: y = x @ W^T -> fp16.  128x128 tile, K-tile 16, 8x8 micro-tile.
// ---------------------------------------------------------------------------
__global__ __launch_bounds__(256, 2)
void gemm_xwt_kernel(const float* __restrict__ x, const float* __restrict__ W,
                     int n_nodes) {
    __shared__ float As[16][128];
    __shared__ float Bs[16][128];

    const int tid = threadIdx.x;
    const int m0  = blockIdx.x * 128;
    const int tx  = tid & 15;
    const int ty  = tid >> 4;

    float acc[8][8];
#pragma unroll
    for (int r = 0; r < 8; r++)
#pragma unroll
        for (int c = 0; c < 8; c++) acc[r][c] = 0.0f;

    const int lr = tid >> 1;         // 0..127 (row within tile)
    const int lk = (tid & 1) * 8;    // 0 or 8 (k octet; 2 float4 each)

    for (int k0 = 0; k0 < F_DIM; k0 += 16) {
        const int gm = m0 + lr;
#pragma unroll
        for (int q = 0; q < 2; q++) {
            float4 av = make_float4(0.f, 0.f, 0.f, 0.f);
            if (gm < n_nodes)
                av = *(const float4*)(x + (size_t)gm * F_DIM + k0 + lk + q * 4);
            As[lk + q * 4 + 0][lr] = av.x;
            As[lk + q * 4 + 1][lr] = av.y;
            As[lk + q * 4 + 2][lr] = av.z;
            As[lk + q * 4 + 3][lr] = av.w;

            float4 bv = *(const float4*)(W + (size_t)lr * F_DIM + k0 + lk + q * 4);
            Bs[lk + q * 4 + 0][lr] = bv.x;
            Bs[lk + q * 4 + 1][lr] = bv.y;
            Bs[lk + q * 4 + 2][lr] = bv.z;
            Bs[lk + q * 4 + 3][lr] = bv.w;
        }
        __syncthreads();

#pragma unroll
        for (int k = 0; k < 16; k++) {
            const float4 a0 = *(const float4*)&As[k][ty * 4];
            const float4 a1 = *(const float4*)&As[k][ty * 4 + 64];
            const float4 b0 = *(const float4*)&Bs[k][tx * 4];
            const float4 b1 = *(const float4*)&Bs[k][tx * 4 + 64];
            const float ar[8] = {a0.x, a0.y, a0.z, a0.w, a1.x, a1.y, a1.z, a1.w};
            const float bc[8] = {b0.x, b0.y, b0.z, b0.w, b1.x, b1.y, b1.z, b1.w};
#pragma unroll
            for (int r = 0; r < 8; r++)
#pragma unroll
                for (int c = 0; c < 8; c++)
                    acc[r][c] = fmaf(ar[r], bc[c], acc[r][c]);
        }
        __syncthreads();
    }

    __half* yh = (__half*)g_yh2;
#pragma unroll
    for (int half_r = 0; half_r < 2; half_r++) {
#pragma unroll
        for (int r = 0; r < 4; r++) {
            const int gm = m0 + ty * 4 + half_r * 64 + r;
            if (gm >= n_nodes) continue;
            const int rr = half_r * 4 + r;
            __half* dst = yh + (size_t)gm * F_DIM;
            half4 h0 = { __float2half_rn(acc[rr][0]), __float2half_rn(acc[rr][1]),
                         __float2half_rn(acc[rr][2]), __float2half_rn(acc[rr][3]) };
            half4 h1 = { __float2half_rn(acc[rr][4]), __float2half_rn(acc[rr][5]),
                         __float2half_rn(acc[rr][6]), __float2half_rn(acc[rr][7]) };
            *(half4*)(dst + tx * 4)      = h0;
            *(half4*)(dst + tx * 4 + 64) = h1;
        }
    }
}

// ---------------------------------------------------------------------------
__global__ void zero_count_kernel(int n_nodes) {
    const int i = blockIdx.x * blockDim.x + threadIdx.x;
    if (i <= n_nodes) g_count[i] = 0;
}

__global__ __launch_bounds__(256)
void hist_kernel(const int* __restrict__ rows, int n_edges) {
    const int e = blockIdx.x * blockDim.x + threadIdx.x;
    if (e < n_edges) atomicAdd(&g_count[rows[e]], 1);
}

__global__ __launch_bounds__(SCAN_BLK)
void scan1_kernel(int n) {
    __shared__ int s[SCAN_BLK];
    const int i = blockIdx.x * SCAN_BLK + threadIdx.x;
    const int v = (i < n) ? g_count[i] : 0;
    s[threadIdx.x] = v;
    __syncthreads();
#pragma unroll
    for (int d = 1; d < SCAN_BLK; d <<= 1) {
        int t = (threadIdx.x >= d) ? s[threadIdx.x - d] : 0;
        __syncthreads();
        s[threadIdx.x] += t;
        __syncthreads();
    }
    if (i < n) g_start[i] = s[threadIdx.x] - v;   // exclusive
    if (threadIdx.x == SCAN_BLK - 1) g_blocksums[blockIdx.x] = s[SCAN_BLK - 1];
}

__global__ void scan2_kernel(int nblocks, int n) {
    if (threadIdx.x == 0 && blockIdx.x == 0) {
        int acc = 0;
        for (int i = 0; i < nblocks; i++) {
            int t = g_blocksums[i];
            g_blocksums[i] = acc;
            acc += t;
        }
        g_start[n] = acc;
    }
}

__global__ __launch_bounds__(256)
void scan3_kernel(int n) {
    const int i = blockIdx.x * blockDim.x + threadIdx.x;
    if (i < n) {
        const int v = g_start[i] + g_blocksums[i >> 10];
        g_start[i]  = v;
        g_cursor[i] = v;
    }
}

__global__ __launch_bounds__(256)
void reorder_kernel(const int* __restrict__ rows, const int* __restrict__ cols,
                    const float* __restrict__ vals, int n_edges) {
    const int e = blockIdx.x * blockDim.x + threadIdx.x;
    if (e < n_edges) {
        const int r = rows[e];
        const int pos = atomicAdd(&g_cursor[r], 1);
        g_edges[pos] = make_int2(cols[e], __float_as_int(vals[e]));
    }
}

// ---------------------------------------------------------------------------
// Accum: one warp per node: out[n] = b + sum_e val_e * y[col_e]
// ---------------------------------------------------------------------------
__global__ __launch_bounds__(256)
void accum_kernel(const float* __restrict__ b, float* __restrict__ out,
                  int n_nodes) {
    const int node = (blockIdx.x * blockDim.x + threadIdx.x) >> 5;
    if (node >= n_nodes) return;
    const int lane = threadIdx.x & 31;

    const int s = g_start[node];
    const int e = g_start[node + 1];

    float a0 = 0.f, a1 = 0.f, a2 = 0.f, a3 = 0.f;

    for (int base = s; base < e; base += 32) {
        const int idx = base + lane;
        int2 ed = make_int2(0, 0);
        if (idx < e) ed = __ldg(&g_edges[idx]);
        const int cnt = min(32, e - base);

        if (cnt == 32) {
#pragma unroll 4
            for (int j = 0; j < 32; j++) {
                const int   col = __shfl_sync(0xffffffffu, ed.x, j);
                const float val = __int_as_float(__shfl_sync(0xffffffffu, ed.y, j));
                const float2 yv = g_yh2[(size_t)col * 32 + lane];
                const float2 f0 = __half22float2(*(const __half2*)&yv.x);
                const float2 f1 = __half22float2(*(const __half2*)&yv.y);
                a0 = fmaf(f0.x, val, a0);
                a1 = fmaf(f0.y, val, a1);
                a2 = fmaf(f1.x, val, a2);
                a3 = fmaf(f1.y, val, a3);
            }
        } else {
            for (int j = 0; j < cnt; j++) {
                const int   col = __shfl_sync(0xffffffffu, ed.x, j);
                const float val = __int_as_float(__shfl_sync(0xffffffffu, ed.y, j));
                const float2 yv = g_yh2[(size_t)col * 32 + lane];
                const float2 f0 = __half22float2(*(const __half2*)&yv.x);
                const float2 f1 = __half22float2(*(const __half2*)&yv.y);
                a0 = fmaf(f0.x, val, a0);
                a1 = fmaf(f0.y, val, a1);
                a2 = fmaf(f1.x, val, a2);
                a3 = fmaf(f1.y, val, a3);
            }
        }
    }

    const float4 bb = *(const float4*)(b + lane * 4);
    *(float4*)(out + (size_t)node * F_DIM + lane * 4) =
        make_float4(a0 + bb.x, a1 + bb.y, a2 + bb.z, a3 + bb.w);
}

// ---------------------------------------------------------------------------
extern "C" void kernel_launch(void* const* d_in, const int* in_sizes, int n_in,
                              void* d_out, int out_size) {
    const int*   rows = (const int*)d_in[0];
    const int*   cols = (const int*)d_in[1];
    const float* vals = (const float*)d_in[2];
    const float* x    = (const float*)d_in[3];
    const float* W    = (const float*)d_in[4];
    const float* b    = (const float*)d_in[5];
    float*       out  = (float*)d_out;

    const int n_edges = in_sizes[0];
    const int n_nodes = in_sizes[3] / F_DIM;
    const int nblocks_scan = (n_nodes + SCAN_BLK - 1) / SCAN_BLK;

    // Side stream + events for a parallel preprocessing branch in the graph.
    // Created once (host-side infra only; per-call GPU work is identical).
    static cudaStream_t s2 = nullptr;
    static cudaEvent_t ev_fork = nullptr, ev_join = nullptr;
    if (s2 == nullptr) {
        cudaStreamCreateWithFlags(&s2, cudaStreamNonBlocking);
        cudaEventCreateWithFlags(&ev_fork, cudaEventDisableTiming);
        cudaEventCreateWithFlags(&ev_join, cudaEventDisableTiming);
    }

    // Fork: side stream joins the (possibly capturing) main stream.
    cudaEventRecord(ev_fork, 0);
    cudaStreamWaitEvent(s2, ev_fork, 0);

    // Branch A (main stream): y = x @ W^T -> fp16
    gemm_xwt_kernel<<<(n_nodes + 127) / 128, 256>>>(x, W, n_nodes);

    // Branch B (side stream): CSR build
    zero_count_kernel<<<(n_nodes + 256) / 256, 256, 0, s2>>>(n_nodes);
    hist_kernel<<<(n_edges + 255) / 256, 256, 0, s2>>>(rows, n_edges);
    scan1_kernel<<<nblocks_scan, SCAN_BLK, 0, s2>>>(n_nodes);
    scan2_kernel<<<1, 32, 0, s2>>>(nblocks_scan, n_nodes);
    scan3_kernel<<<(n_nodes + 255) / 256, 256, 0, s2>>>(n_nodes);
    reorder_kernel<<<(n_edges + 255) / 256, 256, 0, s2>>>(rows, cols, vals, n_edges);

    // Join: main stream waits for branch B.
    cudaEventRecord(ev_join, s2);
    cudaStreamWaitEvent(0, ev_join, 0);

    // Gather-accumulate (depends on both branches), bias fused.
    accum_kernel<<<(n_nodes * 32 + 255) / 256, 256>>>(b, out, n_nodes);
}

// round 6
// speedup vs baseline: 2.8760x; 1.1802x over previous
#include <cuda_runtime.h>
#include <cuda_fp16.h>
#include <cstdint>

#define F_DIM 128
#define MAX_NODES 100000
#define MAX_EDGES 3200000
#define SCAN_BLK 1024
#define MAX_SCAN_BLOCKS ((MAX_NODES + SCAN_BLK - 1) / SCAN_BLK + 2)
#define KT 32
#define SPAD (KT + 4)

// Scratch (__device__ globals per harness rules)
__device__ float2 g_yh2[(size_t)MAX_NODES * (F_DIM / 4)]; // fp16 y (half2 pairs)
__device__ int    g_count[MAX_NODES + 1];
__device__ int    g_start[MAX_NODES + 1];
__device__ int    g_cursor[MAX_NODES];
__device__ int    g_blocksums[MAX_SCAN_BLOCKS];
__device__ int2   g_edges[MAX_EDGES];          // packed (col, val-as-int)

__device__ __forceinline__ uint32_t f32_to_tf32(float f) {
    uint32_t u;
    asm("cvt.rna.tf32.f32 %0, %1;" : "=r"(u) : "f"(f));
    return u;
}

// ---------------------------------------------------------------------------
// Kernel 1: y = x @ W^T -> fp16 via mma.sync tf32 tensor cores.
// Block: 128 rows x 128 cols, 8 warps; warp w -> rows [16w,16w+16), all cols.
// K-tiles of 32 staged in smem (tf32-converted), 4 k8 mma steps per tile.
// ---------------------------------------------------------------------------
__global__ __launch_bounds__(256, 2)
void gemm_tf32_kernel(const float* __restrict__ x, const float* __restrict__ W,
                      int n_nodes) {
    __shared__ uint32_t As[128][SPAD];   // x tile  [m][k], tf32 bits
    __shared__ uint32_t Ws[128][SPAD];   // W tile  [n][k], tf32 bits

    const int tid  = threadIdx.x;
    const int warp = tid >> 5;
    const int lane = tid & 31;
    const int g    = lane >> 2;      // 0..7
    const int t    = lane & 3;       // 0..3
    const int m0   = blockIdx.x * 128;

    float c[16][4];
#pragma unroll
    for (int nt = 0; nt < 16; nt++)
#pragma unroll
        for (int i = 0; i < 4; i++) c[nt][i] = 0.0f;

    for (int kt = 0; kt < F_DIM; kt += KT) {
        // Stage tiles: 128 rows x 32 cols each; 1024 float4 per tile, 4/thread.
#pragma unroll
        for (int i = 0; i < 4; i++) {
            const int idx = tid + i * 256;   // 0..1023
            const int r   = idx >> 3;        // 0..127
            const int cq  = (idx & 7) * 4;   // 0,4,..,28

            float4 av = make_float4(0.f, 0.f, 0.f, 0.f);
            if (m0 + r < n_nodes)
                av = *(const float4*)(x + (size_t)(m0 + r) * F_DIM + kt + cq);
            As[r][cq + 0] = f32_to_tf32(av.x);
            As[r][cq + 1] = f32_to_tf32(av.y);
            As[r][cq + 2] = f32_to_tf32(av.z);
            As[r][cq + 3] = f32_to_tf32(av.w);

            const float4 wv = *(const float4*)(W + (size_t)r * F_DIM + kt + cq);
            Ws[r][cq + 0] = f32_to_tf32(wv.x);
            Ws[r][cq + 1] = f32_to_tf32(wv.y);
            Ws[r][cq + 2] = f32_to_tf32(wv.z);
            Ws[r][cq + 3] = f32_to_tf32(wv.w);
        }
        __syncthreads();

#pragma unroll
        for (int ks = 0; ks < KT; ks += 8) {
            // A fragment (m16n8k8 row-major): rows warp*16+{g, g+8}, cols ks+{t, t+4}
            const uint32_t a0 = As[warp * 16 + g    ][ks + t];
            const uint32_t a1 = As[warp * 16 + g + 8][ks + t];
            const uint32_t a2 = As[warp * 16 + g    ][ks + t + 4];
            const uint32_t a3 = As[warp * 16 + g + 8][ks + t + 4];
#pragma unroll
            for (int nt = 0; nt < 16; nt++) {
                // B fragment (col-major 8x8): B[k][n] = W[n][k]
                const uint32_t b0 = Ws[nt * 8 + g][ks + t];
                const uint32_t b1 = Ws[nt * 8 + g][ks + t + 4];
                asm volatile(
                    "mma.sync.aligned.m16n8k8.row.col.f32.tf32.tf32.f32 "
                    "{%0,%1,%2,%3}, {%4,%5,%6,%7}, {%8,%9}, {%0,%1,%2,%3};"
                    : "+f"(c[nt][0]), "+f"(c[nt][1]), "+f"(c[nt][2]), "+f"(c[nt][3])
                    : "r"(a0), "r"(a1), "r"(a2), "r"(a3), "r"(b0), "r"(b1));
            }
        }
        __syncthreads();
    }

    // Store fp16: c0,c1 -> (row g, cols 2t,2t+1); c2,c3 -> (row g+8).
    __half* yh = (__half*)g_yh2;
    const int r0 = m0 + warp * 16 + g;
    const int r1 = r0 + 8;
#pragma unroll
    for (int nt = 0; nt < 16; nt++) {
        const int col = nt * 8 + 2 * t;
        if (r0 < n_nodes)
            *(__half2*)(yh + (size_t)r0 * F_DIM + col) =
                __floats2half2_rn(c[nt][0], c[nt][1]);
        if (r1 < n_nodes)
            *(__half2*)(yh + (size_t)r1 * F_DIM + col) =
                __floats2half2_rn(c[nt][2], c[nt][3]);
    }
}

// ---------------------------------------------------------------------------
__global__ void zero_count_kernel(int n_nodes) {
    const int i = blockIdx.x * blockDim.x + threadIdx.x;
    if (i <= n_nodes) g_count[i] = 0;
}

__global__ __launch_bounds__(256)
void hist_kernel(const int* __restrict__ rows, int n_edges) {
    const int e = blockIdx.x * blockDim.x + threadIdx.x;
    if (e < n_edges) atomicAdd(&g_count[rows[e]], 1);
}

__global__ __launch_bounds__(SCAN_BLK)
void scan1_kernel(int n) {
    __shared__ int s[SCAN_BLK];
    const int i = blockIdx.x * SCAN_BLK + threadIdx.x;
    const int v = (i < n) ? g_count[i] : 0;
    s[threadIdx.x] = v;
    __syncthreads();
#pragma unroll
    for (int d = 1; d < SCAN_BLK; d <<= 1) {
        int tt = (threadIdx.x >= d) ? s[threadIdx.x - d] : 0;
        __syncthreads();
        s[threadIdx.x] += tt;
        __syncthreads();
    }
    if (i < n) g_start[i] = s[threadIdx.x] - v;   // exclusive
    if (threadIdx.x == SCAN_BLK - 1) g_blocksums[blockIdx.x] = s[SCAN_BLK - 1];
}

__global__ void scan2_kernel(int nblocks, int n) {
    if (threadIdx.x == 0 && blockIdx.x == 0) {
        int acc = 0;
        for (int i = 0; i < nblocks; i++) {
            int t = g_blocksums[i];
            g_blocksums[i] = acc;
            acc += t;
        }
        g_start[n] = acc;
    }
}

__global__ __launch_bounds__(256)
void scan3_kernel(int n) {
    const int i = blockIdx.x * blockDim.x + threadIdx.x;
    if (i < n) {
        const int v = g_start[i] + g_blocksums[i >> 10];
        g_start[i]  = v;
        g_cursor[i] = v;
    }
}

__global__ __launch_bounds__(256)
void reorder_kernel(const int* __restrict__ rows, const int* __restrict__ cols,
                    const float* __restrict__ vals, int n_edges) {
    const int e = blockIdx.x * blockDim.x + threadIdx.x;
    if (e < n_edges) {
        const int r = rows[e];
        const int pos = atomicAdd(&g_cursor[r], 1);
        g_edges[pos] = make_int2(cols[e], __float_as_int(vals[e]));
    }
}

// ---------------------------------------------------------------------------
// Accum: one warp per node: out[n] = b + sum_e val_e * y[col_e]
// ---------------------------------------------------------------------------
__global__ __launch_bounds__(256)
void accum_kernel(const float* __restrict__ b, float* __restrict__ out,
                  int n_nodes) {
    const int node = (blockIdx.x * blockDim.x + threadIdx.x) >> 5;
    if (node >= n_nodes) return;
    const int lane = threadIdx.x & 31;

    const int s = g_start[node];
    const int e = g_start[node + 1];

    float a0 = 0.f, a1 = 0.f, a2 = 0.f, a3 = 0.f;

    for (int base = s; base < e; base += 32) {
        const int idx = base + lane;
        int2 ed = make_int2(0, 0);
        if (idx < e) ed = __ldg(&g_edges[idx]);
        const int cnt = min(32, e - base);

        if (cnt == 32) {
#pragma unroll 8
            for (int j = 0; j < 32; j++) {
                const int   col = __shfl_sync(0xffffffffu, ed.x, j);
                const float val = __int_as_float(__shfl_sync(0xffffffffu, ed.y, j));
                const float2 yv = g_yh2[(size_t)col * 32 + lane];
                const float2 f0 = __half22float2(*(const __half2*)&yv.x);
                const float2 f1 = __half22float2(*(const __half2*)&yv.y);
                a0 = fmaf(f0.x, val, a0);
                a1 = fmaf(f0.y, val, a1);
                a2 = fmaf(f1.x, val, a2);
                a3 = fmaf(f1.y, val, a3);
            }
        } else {
            for (int j = 0; j < cnt; j++) {
                const int   col = __shfl_sync(0xffffffffu, ed.x, j);
                const float val = __int_as_float(__shfl_sync(0xffffffffu, ed.y, j));
                const float2 yv = g_yh2[(size_t)col * 32 + lane];
                const float2 f0 = __half22float2(*(const __half2*)&yv.x);
                const float2 f1 = __half22float2(*(const __half2*)&yv.y);
                a0 = fmaf(f0.x, val, a0);
                a1 = fmaf(f0.y, val, a1);
                a2 = fmaf(f1.x, val, a2);
                a3 = fmaf(f1.y, val, a3);
            }
        }
    }

    const float4 bb = *(const float4*)(b + lane * 4);
    *(float4*)(out + (size_t)node * F_DIM + lane * 4) =
        make_float4(a0 + bb.x, a1 + bb.y, a2 + bb.z, a3 + bb.w);
}

// ---------------------------------------------------------------------------
extern "C" void kernel_launch(void* const* d_in, const int* in_sizes, int n_in,
                              void* d_out, int out_size) {
    const int*   rows = (const int*)d_in[0];
    const int*   cols = (const int*)d_in[1];
    const float* vals = (const float*)d_in[2];
    const float* x    = (const float*)d_in[3];
    const float* W    = (const float*)d_in[4];
    const float* b    = (const float*)d_in[5];
    float*       out  = (float*)d_out;

    const int n_edges = in_sizes[0];
    const int n_nodes = in_sizes[3] / F_DIM;
    const int nblocks_scan = (n_nodes + SCAN_BLK - 1) / SCAN_BLK;

    static cudaStream_t s2 = nullptr;
    static cudaEvent_t ev_fork = nullptr, ev_join = nullptr;
    if (s2 == nullptr) {
        cudaStreamCreateWithFlags(&s2, cudaStreamNonBlocking);
        cudaEventCreateWithFlags(&ev_fork, cudaEventDisableTiming);
        cudaEventCreateWithFlags(&ev_join, cudaEventDisableTiming);
    }

    // Fork
    cudaEventRecord(ev_fork, 0);
    cudaStreamWaitEvent(s2, ev_fork, 0);

    // Branch A (main): y = x @ W^T (tf32 tensor cores) -> fp16
    gemm_tf32_kernel<<<(n_nodes + 127) / 128, 256>>>(x, W, n_nodes);

    // Branch B (side): CSR build
    zero_count_kernel<<<(n_nodes + 256) / 256, 256, 0, s2>>>(n_nodes);
    hist_kernel<<<(n_edges + 255) / 256, 256, 0, s2>>>(rows, n_edges);
    scan1_kernel<<<nblocks_scan, SCAN_BLK, 0, s2>>>(n_nodes);
    scan2_kernel<<<1, 32, 0, s2>>>(nblocks_scan, n_nodes);
    scan3_kernel<<<(n_nodes + 255) / 256, 256, 0, s2>>>(n_nodes);
    reorder_kernel<<<(n_edges + 255) / 256, 256, 0, s2>>>(rows, cols, vals, n_edges);

    // Join
    cudaEventRecord(ev_join, s2);
    cudaStreamWaitEvent(0, ev_join, 0);

    // Gather-accumulate, bias fused.
    accum_kernel<<<(n_nodes * 32 + 255) / 256, 256>>>(b, out, n_nodes);
}

// round 7
// speedup vs baseline: 2.9178x; 1.0145x over previous
#include <cuda_runtime.h>
#include <cuda_fp16.h>
#include <cstdint>

#define F_DIM 128
#define MAX_NODES 100000
#define MAX_EDGES 3200000
#define SCAN_BLK 1024
#define MAX_SCAN_BLOCKS ((MAX_NODES + SCAN_BLK - 1) / SCAN_BLK + 2)
#define KT 32
#define SPAD (KT + 4)

// Scratch (__device__ globals per harness rules)
__device__ float2 g_yh2[(size_t)MAX_NODES * (F_DIM / 4)]; // fp16 y (half2 pairs)
__device__ int    g_count[MAX_NODES + 1];
__device__ int    g_start[MAX_NODES + 1];
__device__ int    g_cursor[MAX_NODES];
__device__ int    g_blocksums[MAX_SCAN_BLOCKS];
__device__ int2   g_edges[MAX_EDGES];          // packed (col, val-as-int)

__device__ __forceinline__ uint32_t f32_to_tf32(float f) {
    uint32_t u;
    asm("cvt.rna.tf32.f32 %0, %1;" : "=r"(u) : "f"(f));
    return u;
}

// ---------------------------------------------------------------------------
// Kernel 1: y = x @ W^T -> fp16 via mma.sync tf32 tensor cores. (R5, proven)
// ---------------------------------------------------------------------------
__global__ __launch_bounds__(256, 2)
void gemm_tf32_kernel(const float* __restrict__ x, const float* __restrict__ W,
                      int n_nodes) {
    __shared__ uint32_t As[128][SPAD];
    __shared__ uint32_t Ws[128][SPAD];

    const int tid  = threadIdx.x;
    const int warp = tid >> 5;
    const int lane = tid & 31;
    const int g    = lane >> 2;
    const int t    = lane & 3;
    const int m0   = blockIdx.x * 128;

    float c[16][4];
#pragma unroll
    for (int nt = 0; nt < 16; nt++)
#pragma unroll
        for (int i = 0; i < 4; i++) c[nt][i] = 0.0f;

    for (int kt = 0; kt < F_DIM; kt += KT) {
#pragma unroll
        for (int i = 0; i < 4; i++) {
            const int idx = tid + i * 256;
            const int r   = idx >> 3;
            const int cq  = (idx & 7) * 4;

            float4 av = make_float4(0.f, 0.f, 0.f, 0.f);
            if (m0 + r < n_nodes)
                av = *(const float4*)(x + (size_t)(m0 + r) * F_DIM + kt + cq);
            As[r][cq + 0] = f32_to_tf32(av.x);
            As[r][cq + 1] = f32_to_tf32(av.y);
            As[r][cq + 2] = f32_to_tf32(av.z);
            As[r][cq + 3] = f32_to_tf32(av.w);

            const float4 wv = *(const float4*)(W + (size_t)r * F_DIM + kt + cq);
            Ws[r][cq + 0] = f32_to_tf32(wv.x);
            Ws[r][cq + 1] = f32_to_tf32(wv.y);
            Ws[r][cq + 2] = f32_to_tf32(wv.z);
            Ws[r][cq + 3] = f32_to_tf32(wv.w);
        }
        __syncthreads();

#pragma unroll
        for (int ks = 0; ks < KT; ks += 8) {
            const uint32_t a0 = As[warp * 16 + g    ][ks + t];
            const uint32_t a1 = As[warp * 16 + g + 8][ks + t];
            const uint32_t a2 = As[warp * 16 + g    ][ks + t + 4];
            const uint32_t a3 = As[warp * 16 + g + 8][ks + t + 4];
#pragma unroll
            for (int nt = 0; nt < 16; nt++) {
                const uint32_t b0 = Ws[nt * 8 + g][ks + t];
                const uint32_t b1 = Ws[nt * 8 + g][ks + t + 4];
                asm volatile(
                    "mma.sync.aligned.m16n8k8.row.col.f32.tf32.tf32.f32 "
                    "{%0,%1,%2,%3}, {%4,%5,%6,%7}, {%8,%9}, {%0,%1,%2,%3};"
                    : "+f"(c[nt][0]), "+f"(c[nt][1]), "+f"(c[nt][2]), "+f"(c[nt][3])
                    : "r"(a0), "r"(a1), "r"(a2), "r"(a3), "r"(b0), "r"(b1));
            }
        }
        __syncthreads();
    }

    __half* yh = (__half*)g_yh2;
    const int r0 = m0 + warp * 16 + g;
    const int r1 = r0 + 8;
#pragma unroll
    for (int nt = 0; nt < 16; nt++) {
        const int col = nt * 8 + 2 * t;
        if (r0 < n_nodes)
            *(__half2*)(yh + (size_t)r0 * F_DIM + col) =
                __floats2half2_rn(c[nt][0], c[nt][1]);
        if (r1 < n_nodes)
            *(__half2*)(yh + (size_t)r1 * F_DIM + col) =
                __floats2half2_rn(c[nt][2], c[nt][3]);
    }
}

// ---------------------------------------------------------------------------
__global__ void zero_count_kernel(int n_nodes) {
    const int i = blockIdx.x * blockDim.x + threadIdx.x;
    if (i <= n_nodes) g_count[i] = 0;
}

// hist: 4 edges per thread (int4), streaming loads.
__global__ __launch_bounds__(256)
void hist_kernel(const int* __restrict__ rows, int n_edges) {
    const int base = (blockIdx.x * blockDim.x + threadIdx.x) * 4;
    if (base + 3 < n_edges) {
        const int4 r4 = __ldcs((const int4*)(rows + base));
        atomicAdd(&g_count[r4.x], 1);
        atomicAdd(&g_count[r4.y], 1);
        atomicAdd(&g_count[r4.z], 1);
        atomicAdd(&g_count[r4.w], 1);
    } else {
        for (int e = base; e < n_edges; e++)
            atomicAdd(&g_count[__ldcs(rows + e)], 1);
    }
}

__global__ __launch_bounds__(SCAN_BLK)
void scan1_kernel(int n) {
    __shared__ int s[SCAN_BLK];
    const int i = blockIdx.x * SCAN_BLK + threadIdx.x;
    const int v = (i < n) ? g_count[i] : 0;
    s[threadIdx.x] = v;
    __syncthreads();
#pragma unroll
    for (int d = 1; d < SCAN_BLK; d <<= 1) {
        int tt = (threadIdx.x >= d) ? s[threadIdx.x - d] : 0;
        __syncthreads();
        s[threadIdx.x] += tt;
        __syncthreads();
    }
    if (i < n) g_start[i] = s[threadIdx.x] - v;
    if (threadIdx.x == SCAN_BLK - 1) g_blocksums[blockIdx.x] = s[SCAN_BLK - 1];
}

__global__ void scan2_kernel(int nblocks, int n) {
    if (threadIdx.x == 0 && blockIdx.x == 0) {
        int acc = 0;
        for (int i = 0; i < nblocks; i++) {
            int t = g_blocksums[i];
            g_blocksums[i] = acc;
            acc += t;
        }
        g_start[n] = acc;
    }
}

__global__ __launch_bounds__(256)
void scan3_kernel(int n) {
    const int i = blockIdx.x * blockDim.x + threadIdx.x;
    if (i < n) {
        const int v = g_start[i] + g_blocksums[i >> 10];
        g_start[i]  = v;
        g_cursor[i] = v;
    }
}

__global__ __launch_bounds__(256)
void reorder_kernel(const int* __restrict__ rows, const int* __restrict__ cols,
                    const float* __restrict__ vals, int n_edges) {
    const int e = blockIdx.x * blockDim.x + threadIdx.x;
    if (e < n_edges) {
        const int   r = __ldcs(rows + e);
        const int   c = __ldcs(cols + e);
        const float v = __ldcs(vals + e);
        const int pos = atomicAdd(&g_cursor[r], 1);
        g_edges[pos] = make_int2(c, __float_as_int(v));
    }
}

// ---------------------------------------------------------------------------
// Accum: one warp per node: out[n] = b + sum_e val_e * y[col_e]
// Streaming edge reads (__ldcs), evict-first out stores (__stcs).
// ---------------------------------------------------------------------------
__global__ __launch_bounds__(256)
void accum_kernel(const float* __restrict__ b, float* __restrict__ out,
                  int n_nodes) {
    const int node = (blockIdx.x * blockDim.x + threadIdx.x) >> 5;
    if (node >= n_nodes) return;
    const int lane = threadIdx.x & 31;

    const int s = g_start[node];
    const int e = g_start[node + 1];

    float a0 = 0.f, a1 = 0.f, a2 = 0.f, a3 = 0.f;

    for (int base = s; base < e; base += 32) {
        const int idx = base + lane;
        int2 ed = make_int2(0, 0);
        if (idx < e) ed = __ldcs(&g_edges[idx]);
        const int cnt = min(32, e - base);

        if (cnt == 32) {
#pragma unroll 16
            for (int j = 0; j < 32; j++) {
                const int   col = __shfl_sync(0xffffffffu, ed.x, j);
                const float val = __int_as_float(__shfl_sync(0xffffffffu, ed.y, j));
                const float2 yv = g_yh2[(size_t)col * 32 + lane];
                const float2 f0 = __half22float2(*(const __half2*)&yv.x);
                const float2 f1 = __half22float2(*(const __half2*)&yv.y);
                a0 = fmaf(f0.x, val, a0);
                a1 = fmaf(f0.y, val, a1);
                a2 = fmaf(f1.x, val, a2);
                a3 = fmaf(f1.y, val, a3);
            }
        } else {
            for (int j = 0; j < cnt; j++) {
                const int   col = __shfl_sync(0xffffffffu, ed.x, j);
                const float val = __int_as_float(__shfl_sync(0xffffffffu, ed.y, j));
                const float2 yv = g_yh2[(size_t)col * 32 + lane];
                const float2 f0 = __half22float2(*(const __half2*)&yv.x);
                const float2 f1 = __half22float2(*(const __half2*)&yv.y);
                a0 = fmaf(f0.x, val, a0);
                a1 = fmaf(f0.y, val, a1);
                a2 = fmaf(f1.x, val, a2);
                a3 = fmaf(f1.y, val, a3);
            }
        }
    }

    const float4 bb = *(const float4*)(b + lane * 4);
    __stcs((float4*)(out + (size_t)node * F_DIM + lane * 4),
           make_float4(a0 + bb.x, a1 + bb.y, a2 + bb.z, a3 + bb.w));
}

// ---------------------------------------------------------------------------
extern "C" void kernel_launch(void* const* d_in, const int* in_sizes, int n_in,
                              void* d_out, int out_size) {
    const int*   rows = (const int*)d_in[0];
    const int*   cols = (const int*)d_in[1];
    const float* vals = (const float*)d_in[2];
    const float* x    = (const float*)d_in[3];
    const float* W    = (const float*)d_in[4];
    const float* b    = (const float*)d_in[5];
    float*       out  = (float*)d_out;

    const int n_edges = in_sizes[0];
    const int n_nodes = in_sizes[3] / F_DIM;
    const int nblocks_scan = (n_nodes + SCAN_BLK - 1) / SCAN_BLK;

    static cudaStream_t s2 = nullptr;
    static cudaEvent_t ev_fork = nullptr, ev_join = nullptr;
    if (s2 == nullptr) {
        cudaStreamCreateWithFlags(&s2, cudaStreamNonBlocking);
        cudaEventCreateWithFlags(&ev_fork, cudaEventDisableTiming);
        cudaEventCreateWithFlags(&ev_join, cudaEventDisableTiming);
    }

    // Fork: GEMM goes to the side stream (short branch).
    cudaEventRecord(ev_fork, 0);
    cudaStreamWaitEvent(s2, ev_fork, 0);

    // Branch A (side): y = x @ W^T (tf32 tensor cores) -> fp16
    gemm_tf32_kernel<<<(n_nodes + 127) / 128, 256, 0, s2>>>(x, W, n_nodes);

    // Branch B (main, critical): CSR build
    zero_count_kernel<<<(n_nodes + 256) / 256, 256>>>(n_nodes);
    {
        const int threads_needed = (n_edges + 3) / 4;
        hist_kernel<<<(threads_needed + 255) / 256, 256>>>(rows, n_edges);
    }
    scan1_kernel<<<nblocks_scan, SCAN_BLK>>>(n_nodes);
    scan2_kernel<<<1, 32>>>(nblocks_scan, n_nodes);
    scan3_kernel<<<(n_nodes + 255) / 256, 256>>>(n_nodes);
    reorder_kernel<<<(n_edges + 255) / 256, 256>>>(rows, cols, vals, n_edges);

    // Join: main waits for GEMM.
    cudaEventRecord(ev_join, s2);
    cudaStreamWaitEvent(0, ev_join, 0);

    // Gather-accumulate, bias fused.
    accum_kernel<<<(n_nodes * 32 + 255) / 256, 256>>>(b, out, n_nodes);
}